// round 3
// baseline (speedup 1.0000x reference)
#include <cuda_runtime.h>
#include <math.h>

#define HOPS 2
#define BB   2048
#define MM   64
#define DD   16
#define NREL 32
#define PAD  17          // q row stride, coprime with 32 -> conflict-free random-row reads

__global__ __launch_bounds__(256, 8)
void ripplenet_kernel(const int*   __restrict__ items,
                      const int*   __restrict__ heads,
                      const int*   __restrict__ relations,
                      const int*   __restrict__ tails,
                      const float* __restrict__ ent_emb,
                      const float* __restrict__ rel_emb,
                      float*       __restrict__ out)
{
    const int blk  = blockIdx.x;          // 0..1023, two batch items per block
    const int b0   = blk * 2;
    const int tid  = threadIdx.x;
    const int lane = tid & 31;
    const int wid  = tid >> 5;            // 0..7
    const int bt   = tid >> 7;            // which batch: 0 or 1
    const int h    = (tid >> 6) & 1;      // hop
    const int m    = tid & 63;            // memory slot

    __shared__ float s_item[2][DD];
    __shared__ float s_q[2][NREL * PAD];
    __shared__ float s_red[8][2];         // per warp: {E, S}

    // ---- indices for this thread's single (batch, h, m) slot ----
    const int idx = h * (BB * MM) + (b0 + bt) * MM + m;
    const int he  = __ldg(heads + idx);
    const int re  = __ldg(relations + idx);
    const int te  = __ldg(tails + idx);

    // ---- issue ALL embedding gathers NOW; consumed only after the q-phase ----
    const float4* hp = (const float4*)(ent_emb + (size_t)he * DD);
    const float4* tp = (const float4*)(ent_emb + (size_t)te * DD);
    float4 h0 = __ldg(hp + 0), h1 = __ldg(hp + 1), h2 = __ldg(hp + 2), h3 = __ldg(hp + 3);
    float4 t0 = __ldg(tp + 0), t1 = __ldg(tp + 1), t2 = __ldg(tp + 2), t3 = __ldg(tp + 3);

    // ---- load both item embeddings into smem ----
    if (tid < 32) {
        const int which = tid >> 4;
        const int it    = items[b0 + which];
        s_item[which][tid & 15] = ent_emb[(size_t)it * DD + (tid & 15)];
    }
    __syncthreads();

    // ---- q[bt][r][j0..j0+3] = sum_i item_bt[i] * R[r][i][j], one strip per thread ----
    // 256 threads = 2 batches x 32 rel x 4 strips. R loads hit L2 (32KB hot).
    {
        const int qb = tid >> 7;                       // batch this strip belongs to
        const int r  = (tid >> 2) & 31;
        const int j0 = (tid & 3) * 4;
        const float4* Rp = (const float4*)(rel_emb + (size_t)r * DD * DD + j0);
        float4 q = make_float4(0.f, 0.f, 0.f, 0.f);
        #pragma unroll
        for (int i = 0; i < DD; i++) {
            const float4 Rv = __ldg(Rp + i * 4);       // R[r][i][j0..j0+3]
            const float it  = s_item[qb][i];
            q.x = fmaf(it, Rv.x, q.x); q.y = fmaf(it, Rv.y, q.y);
            q.z = fmaf(it, Rv.z, q.z); q.w = fmaf(it, Rv.w, q.w);
        }
        float* qp = &s_q[qb][r * PAD + j0];
        qp[0] = q.x; qp[1] = q.y; qp[2] = q.z; qp[3] = q.w;
    }
    __syncthreads();

    // ---- consume gathers: logit = dot(q[rel], head), tdot = dot(tail, item) ----
    float logit = 0.f, tdot = 0.f;
    {
        const float* qr = &s_q[bt][re * PAD];          // stride-17: conflict-free
        const float* it = s_item[bt];
        logit = fmaf(qr[0],  h0.x, logit); logit = fmaf(qr[1],  h0.y, logit);
        logit = fmaf(qr[2],  h0.z, logit); logit = fmaf(qr[3],  h0.w, logit);
        logit = fmaf(qr[4],  h1.x, logit); logit = fmaf(qr[5],  h1.y, logit);
        logit = fmaf(qr[6],  h1.z, logit); logit = fmaf(qr[7],  h1.w, logit);
        logit = fmaf(qr[8],  h2.x, logit); logit = fmaf(qr[9],  h2.y, logit);
        logit = fmaf(qr[10], h2.z, logit); logit = fmaf(qr[11], h2.w, logit);
        logit = fmaf(qr[12], h3.x, logit); logit = fmaf(qr[13], h3.y, logit);
        logit = fmaf(qr[14], h3.z, logit); logit = fmaf(qr[15], h3.w, logit);

        tdot = fmaf(it[0],  t0.x, tdot); tdot = fmaf(it[1],  t0.y, tdot);
        tdot = fmaf(it[2],  t0.z, tdot); tdot = fmaf(it[3],  t0.w, tdot);
        tdot = fmaf(it[4],  t1.x, tdot); tdot = fmaf(it[5],  t1.y, tdot);
        tdot = fmaf(it[6],  t1.z, tdot); tdot = fmaf(it[7],  t1.w, tdot);
        tdot = fmaf(it[8],  t2.x, tdot); tdot = fmaf(it[9],  t2.y, tdot);
        tdot = fmaf(it[10], t2.z, tdot); tdot = fmaf(it[11], t2.w, tdot);
        tdot = fmaf(it[12], t3.x, tdot); tdot = fmaf(it[13], t3.y, tdot);
        tdot = fmaf(it[14], t3.z, tdot); tdot = fmaf(it[15], t3.w, tdot);
    }

    // ---- softmax folded to scalar sums: sigmoid( sum_h (sum_m e*tdot)/(sum_m e) )
    // logits are O(1): exp cannot overflow, max-subtraction skipped.
    float E = __expf(logit);
    float S = E * tdot;

    #pragma unroll
    for (int o = 16; o > 0; o >>= 1) {
        E += __shfl_xor_sync(0xffffffffu, E, o);
        S += __shfl_xor_sync(0xffffffffu, S, o);
    }
    if (lane == 0) { s_red[wid][0] = E; s_red[wid][1] = S; }
    __syncthreads();

    // warp layout: {0,1}=b0h0 {2,3}=b0h1 {4,5}=b1h0 {6,7}=b1h1
    if (tid < 2) {
        const int w  = tid * 4;
        const float E0 = s_red[w][0]     + s_red[w + 1][0];
        const float S0 = s_red[w][1]     + s_red[w + 1][1];
        const float E1 = s_red[w + 2][0] + s_red[w + 3][0];
        const float S1 = s_red[w + 2][1] + s_red[w + 3][1];
        const float u  = S0 / E0 + S1 / E1;
        out[b0 + tid] = 1.f / (1.f + __expf(-u));
    }
}

extern "C" void kernel_launch(void* const* d_in, const int* in_sizes, int n_in,
                              void* d_out, int out_size)
{
    const int*   items     = (const int*)  d_in[0];
    const int*   heads     = (const int*)  d_in[1];
    const int*   relations = (const int*)  d_in[2];
    const int*   tails     = (const int*)  d_in[3];
    const float* ent_emb   = (const float*)d_in[4];
    const float* rel_emb   = (const float*)d_in[5];
    float* out = (float*)d_out;

    ripplenet_kernel<<<BB / 2, 256>>>(items, heads, relations, tails,
                                      ent_emb, rel_emb, out);
}

// round 4
// speedup vs baseline: 1.1165x; 1.1165x over previous
#include <cuda_runtime.h>
#include <math.h>

#define HOPS  2
#define BB    2048
#define MM    64
#define DD    16
#define NREL  32
#define QSTR  17      // smem q row stride (floats), odd -> decorrelated banks

// Precomputed q[b][r][j] = sum_i item_b[i] * R[r][i][j]   (4 MB scratch)
__device__ float q_scratch[BB * NREL * DD];

// ---------------------------------------------------------------------------
// Kernel 1: q precompute. 4 batches per block, R loads amortized 4x.
// ---------------------------------------------------------------------------
__global__ __launch_bounds__(128, 8)
void q_kernel(const int*   __restrict__ items,
              const float* __restrict__ ent_emb,
              const float* __restrict__ rel_emb)
{
    const int b0  = blockIdx.x * 4;
    const int tid = threadIdx.x;

    __shared__ float s_item[4][DD];
    if (tid < 64) {
        const int w  = tid >> 4;
        const int it = __ldg(items + b0 + w);
        s_item[w][tid & 15] = __ldg(ent_emb + (size_t)it * DD + (tid & 15));
    }
    __syncthreads();

    // thread owns strip (r, j0..j0+3) for all 4 batches
    const int r  = tid >> 2;
    const int j0 = (tid & 3) * 4;
    const float4* Rp = (const float4*)(rel_emb + (size_t)r * DD * DD + j0);

    float4 a0 = make_float4(0.f,0.f,0.f,0.f), a1 = a0, a2 = a0, a3 = a0;
    #pragma unroll
    for (int i = 0; i < DD; i++) {
        const float4 Rv = __ldg(Rp + i * 4);   // R[r][i][j0..j0+3]
        const float i0 = s_item[0][i], i1 = s_item[1][i];
        const float i2 = s_item[2][i], i3 = s_item[3][i];
        a0.x = fmaf(i0, Rv.x, a0.x); a0.y = fmaf(i0, Rv.y, a0.y);
        a0.z = fmaf(i0, Rv.z, a0.z); a0.w = fmaf(i0, Rv.w, a0.w);
        a1.x = fmaf(i1, Rv.x, a1.x); a1.y = fmaf(i1, Rv.y, a1.y);
        a1.z = fmaf(i1, Rv.z, a1.z); a1.w = fmaf(i1, Rv.w, a1.w);
        a2.x = fmaf(i2, Rv.x, a2.x); a2.y = fmaf(i2, Rv.y, a2.y);
        a2.z = fmaf(i2, Rv.z, a2.z); a2.w = fmaf(i2, Rv.w, a2.w);
        a3.x = fmaf(i3, Rv.x, a3.x); a3.y = fmaf(i3, Rv.y, a3.y);
        a3.z = fmaf(i3, Rv.z, a3.z); a3.w = fmaf(i3, Rv.w, a3.w);
    }
    float4* qv = (float4*)q_scratch;           // batch tile = 128 float4
    qv[(size_t)(b0 + 0) * 128 + tid] = a0;     // pos = r*4 + (tid&3) = tid
    qv[(size_t)(b0 + 1) * 128 + tid] = a1;
    qv[(size_t)(b0 + 2) * 128 + tid] = a2;
    qv[(size_t)(b0 + 3) * 128 + tid] = a3;
}

// ---------------------------------------------------------------------------
// Kernel 2: main. 2 batches/block, 256 threads, quad-cooperative gathers.
// Quad (4 lanes) owns one (bt,h,m) slot per pass; lane j loads float4 quarter j.
// ---------------------------------------------------------------------------
__global__ __launch_bounds__(256, 4)
void ripplenet_kernel(const int*   __restrict__ items,
                      const int*   __restrict__ heads,
                      const int*   __restrict__ relations,
                      const int*   __restrict__ tails,
                      const float* __restrict__ ent_emb,
                      float*       __restrict__ out)
{
    const int b0   = blockIdx.x * 2;
    const int tid  = threadIdx.x;
    const int lane = tid & 31;
    const int wid  = tid >> 5;        // 0..7
    const int j    = tid & 3;         // float4 quarter owned by this lane
    const int row  = tid >> 2;        // memory slot m (0..63) for every pass

    __shared__ float s_item[2][DD];
    __shared__ float s_q[2][NREL * QSTR];
    __shared__ float s_red[4][8][2];  // [pass][warp]{E,S}

    // ---- indices: pass p -> (bt = p>>1, h = p&1), slot m = row ----
    int he[4], re[4], te[4];
    #pragma unroll
    for (int p = 0; p < 4; p++) {
        const int bt  = p >> 1;
        const int h   = p & 1;
        const int idx = h * (BB * MM) + (b0 + bt) * MM + row;
        he[p] = __ldg(heads + idx);
        re[p] = __ldg(relations + idx);
        te[p] = __ldg(tails + idx);
    }

    // ---- issue ALL gathers: lane j takes quarter j of each row ----
    float4 hq[4], tq[4];
    #pragma unroll
    for (int p = 0; p < 4; p++) {
        hq[p] = __ldg((const float4*)(ent_emb + (size_t)he[p] * DD) + j);
        tq[p] = __ldg((const float4*)(ent_emb + (size_t)te[p] * DD) + j);
    }

    // ---- item embeddings -> smem ----
    if (tid < 32) {
        const int w  = tid >> 4;
        const int it = __ldg(items + b0 + w);
        s_item[w][tid & 15] = __ldg(ent_emb + (size_t)it * DD + (tid & 15));
    }

    // ---- q tiles (precomputed): 2 x 512 floats, coalesced, restrided to 17 ----
    {
        const int bt  = tid >> 7;           // first 128 threads -> batch 0
        const int off = (tid & 127) * 4;    // float offset within batch tile
        const float4 v = *(const float4*)(q_scratch + (size_t)(b0 + bt) * (NREL * DD) + off);
        float* dst = &s_q[bt][(off >> 4) * QSTR + (off & 15)];
        dst[0] = v.x; dst[1] = v.y; dst[2] = v.z; dst[3] = v.w;
    }
    __syncthreads();

    // ---- consume: partial dots over this lane's 4 dims, quad-reduce ----
    #pragma unroll
    for (int p = 0; p < 4; p++) {
        const int bt = p >> 1;
        const float* qr = &s_q[bt][re[p] * QSTR + j * 4];
        const float* it = &s_item[bt][j * 4];

        float pd = 0.f, td = 0.f;
        pd = fmaf(qr[0], hq[p].x, pd); pd = fmaf(qr[1], hq[p].y, pd);
        pd = fmaf(qr[2], hq[p].z, pd); pd = fmaf(qr[3], hq[p].w, pd);
        td = fmaf(it[0], tq[p].x, td); td = fmaf(it[1], tq[p].y, td);
        td = fmaf(it[2], tq[p].z, td); td = fmaf(it[3], tq[p].w, td);

        // quad butterfly: all 4 lanes end with full logit / tdot of their slot
        pd += __shfl_xor_sync(0xffffffffu, pd, 1);
        pd += __shfl_xor_sync(0xffffffffu, pd, 2);
        td += __shfl_xor_sync(0xffffffffu, td, 1);
        td += __shfl_xor_sync(0xffffffffu, td, 2);

        // logits are O(1): exp safe without max-subtraction
        float E = __expf(pd);
        float S = E * td;

        // full-warp butterfly: each slot counted 4x -> cancels in S/E ratio
        #pragma unroll
        for (int o = 4; o < 32; o <<= 1) {
            E += __shfl_xor_sync(0xffffffffu, E, o);
            S += __shfl_xor_sync(0xffffffffu, S, o);
        }
        if (lane == 0) { s_red[p][wid][0] = E; s_red[p][wid][1] = S; }
    }
    __syncthreads();

    // ---- finalize: thread t -> batch b0+t; passes 2t (hop0), 2t+1 (hop1) ----
    if (tid < 2) {
        float u = 0.f;
        #pragma unroll
        for (int h = 0; h < 2; h++) {
            const int p = tid * 2 + h;
            float E = 0.f, S = 0.f;
            #pragma unroll
            for (int w = 0; w < 8; w++) { E += s_red[p][w][0]; S += s_red[p][w][1]; }
            u += S / E;
        }
        out[b0 + tid] = 1.f / (1.f + __expf(-u));
    }
}

extern "C" void kernel_launch(void* const* d_in, const int* in_sizes, int n_in,
                              void* d_out, int out_size)
{
    const int*   items     = (const int*)  d_in[0];
    const int*   heads     = (const int*)  d_in[1];
    const int*   relations = (const int*)  d_in[2];
    const int*   tails     = (const int*)  d_in[3];
    const float* ent_emb   = (const float*)d_in[4];
    const float* rel_emb   = (const float*)d_in[5];
    float* out = (float*)d_out;

    q_kernel<<<BB / 4, 128>>>(items, ent_emb, rel_emb);
    ripplenet_kernel<<<BB / 2, 256>>>(items, heads, relations, tails, ent_emb, out);
}